// round 13
// baseline (speedup 1.0000x reference)
#include <cuda_runtime.h>
#include <cuda_bf16.h>
#include <math.h>
#include <stdint.h>

// Problem constants (reference: N=1024, L=30, G=10000, NB=64)
#define LDIM    30
#define ZROW    32           // padded z row (2 zero pads) -> LDS.128 inner loop
#define GPB     128          // genes per tile (= THREADS, 1 gene/thread)
#define THREADS 128
#define XG      20           // tile groups: block x handles tiles x, x+20, x+40, ...
#define CHUNK   64           // cells staged per z chunk (ncell~16 -> 1 chunk)
#define NMAX    1024

__device__ __forceinline__ float softplus_fast(float x) {
    // max(x,0) + log1p(exp(-|x|)); fast intrinsics (rel err ~1e-6 << 1e-3 budget)
    return fmaxf(x, 0.0f) + __logf(1.0f + __expf(-fabsf(x)));
}

__device__ __forceinline__ void cp_async16(unsigned int saddr, const void* gptr) {
    asm volatile("cp.async.cg.shared.global [%0], [%1], 16;\n" :: "r"(saddr), "l"(gptr));
}
__device__ __forceinline__ void cp_commit() { asm volatile("cp.async.commit_group;\n" ::: "memory"); }
__device__ __forceinline__ void cp_wait0()  { asm volatile("cp.async.wait_group 0;\n" ::: "memory"); }

// ---------------------------------------------------------------------------
// grid = (XG, NB + 1), block = 128.
//   y <  NB : block (x, b) = batch b, gene tiles {x, x+XG, x+2XG, ...}.
//             Compaction + z staging once per block; A tiles double-buffered
//             via cp.async across the tile loop (latency hidden by compute).
//   y == NB : inverse_dispersion = exp(px_r)
// ---------------------------------------------------------------------------
__global__ __launch_bounds__(THREADS, 5) void fused_decoder_kernel(
    const float* __restrict__ z,      // [N, L]
    const int*   __restrict__ bc,     // [N]
    const float* __restrict__ sf,     // [N, 1]
    const float* __restrict__ W,      // [L, G]
    const float* __restrict__ A,      // [NB, G, L]
    const float* __restrict__ bemb,   // [NB, G]
    const float* __restrict__ px_r,   // [G]
    float* __restrict__ out,          // [N, G] ++ [G]
    int N, int G, int NB)
{
    // ---- exp(px_r) slice ----
    if (blockIdx.y == (unsigned)NB) {
        float* od = out + (size_t)N * G;
        for (int g = blockIdx.x * THREADS + threadIdx.x; g < G; g += gridDim.x * THREADS)
            od[g] = __expf(px_r[g]);
        return;
    }

    __shared__ float as[2][GPB * LDIM];     // 30 KB  double-buffered A tiles
    __shared__ float zs[CHUNK * ZROW];      //  8 KB  z chunk, padded rows
    __shared__ int   cells[NMAX + 2];       //  4 KB  cell list (padded to even)
    __shared__ float sfs[CHUNK];
    __shared__ int   scount;

    const int tid = threadIdx.x;
    const int b   = blockIdx.y;
    const int xg  = blockIdx.x;
    const int NT  = (G + GPB - 1) / GPB;    // 79 tiles for G=10000
    if (xg >= NT) return;

    // A tile prefetch helper: tile t -> buffer buf
    auto prefetch_tile = [&](int t, int buf) {
        const int nst = min(GPB, G - t * GPB);
        const float4* src4 = (const float4*)(A + ((size_t)b * G + (size_t)t * GPB) * LDIM);
        unsigned int  dst  = (unsigned int)__cvta_generic_to_shared(&as[buf][0]);
        const int w4 = (nst * LDIM) >> 2;   // nst*30 divisible by 4
        for (int i = tid; i < w4; i += THREADS) cp_async16(dst + i * 16, src4 + i);
    };

    // ---- kick off tile 0's A load first (hides behind compaction) ----
    prefetch_tile(xg, 0);
    cp_commit();

    // ---- compact this batch's cell list once (bc: 4 KB, L2-hot) ----
    if (tid == 0) scount = 0;
    __syncthreads();
    for (int n = tid; n < N; n += THREADS) {
        if (bc[n] == b) {
            int p = atomicAdd(&scount, 1);
            cells[p] = n;
        }
    }
    __syncthreads();
    const int ncell = scount;
    if (ncell == 0) { cp_wait0(); return; }     // uniform across block
    const int ncp = (ncell + 1) & ~1;           // pad to even
    if (tid == 0 && ncp != ncell) cells[ncell] = cells[ncell - 1];

    const int g   = (size_t)0 + tid;            // per-tile gene = t*GPB + tid
    float c[ZROW];
    c[30] = 0.0f; c[31] = 0.0f;

    // ---- chunk loop over cells (normally a single iteration) ----
    for (int cc = 0; cc < ncp; cc += CHUNK) {
        const int nc = min(CHUNK, ncp - cc);
        __syncthreads();                        // zs / as readers from prev chunk done
        if (cc > 0) { prefetch_tile(xg, 0); cp_commit(); }   // rare: re-pipeline

        // stage z rows (padded to 32, zero pads) + size factors for this chunk
        for (int i = tid; i < nc * (LDIM / 2); i += THREADS) {
            int ci = i / (LDIM / 2), l = i - ci * (LDIM / 2);
            float2 v = *(const float2*)(z + (size_t)cells[cc + ci] * LDIM + 2 * l);
            *(float2*)(zs + ci * ZROW + 2 * l) = v;
        }
        for (int i = tid; i < nc; i += THREADS) {
            zs[i * ZROW + 30] = 0.0f;
            zs[i * ZROW + 31] = 0.0f;
            sfs[i] = sf[cells[cc + i]];
        }

        // ---- tile loop: double-buffered A, one sync per tile ----
        int i = 0;
        for (int t = xg; t < NT; t += XG, i++) {
            cp_wait0();
            __syncthreads();                    // as[i&1] arrived + zs staged visible

            const int  nst = min(GPB, G - t * GPB);
            const int  gt  = t * GPB + tid;
            const bool act = (tid < nst);
            float bias = 0.0f;
            if (act) {
                const float* ap = &as[i & 1][tid * LDIM];
                #pragma unroll
                for (int l = 0; l < LDIM; l++)
                    c[l] = W[(size_t)l * G + gt] + ap[l];   // coalesced, L2-hot
                bias = bemb[(size_t)b * G + gt];
            }

            // issue next tile's prefetch: targets the OTHER buffer, whose last
            // readers (iter i-1 coeff build) all passed the sync above -> safe
            if (t + XG < NT) { prefetch_tile(t + XG, (i + 1) & 1); cp_commit(); }

            if (act) {
                for (int j = 0; j < nc; j += 2) {
                    const float4* z0 = (const float4*)(zs + (j    ) * ZROW);
                    const float4* z1 = (const float4*)(zs + (j + 1) * ZROW);
                    float a0 = bias, a1 = bias;
                    #pragma unroll
                    for (int q = 0; q < ZROW / 4; q++) {
                        float4 v0 = z0[q], v1 = z1[q];     // broadcast LDS.128
                        a0 = fmaf(c[4*q+0], v0.x, a0);  a1 = fmaf(c[4*q+0], v1.x, a1);
                        a0 = fmaf(c[4*q+1], v0.y, a0);  a1 = fmaf(c[4*q+1], v1.y, a1);
                        a0 = fmaf(c[4*q+2], v0.z, a0);  a1 = fmaf(c[4*q+2], v1.z, a1);
                        a0 = fmaf(c[4*q+3], v0.w, a0);  a1 = fmaf(c[4*q+3], v1.w, a1);
                    }
                    // duplicate-padded cell stores the same value twice: benign
                    out[(size_t)cells[cc + j    ] * G + gt] = softplus_fast(a0) * sfs[j    ];
                    out[(size_t)cells[cc + j + 1] * G + gt] = softplus_fast(a1) * sfs[j + 1];
                }
            }
        }
    }
}

// ---------------------------------------------------------------------------
// Inputs (metadata order): z, batch_covariate, size_factor, W_amat, A_emb,
//                          b_emb, px_r.  Output: mean [N,G] ++ inv_disp [G].
// ---------------------------------------------------------------------------
extern "C" void kernel_launch(void* const* d_in, const int* in_sizes, int n_in,
                              void* d_out, int out_size) {
    const float* z    = (const float*)d_in[0];
    const int*   bc   = (const int*)  d_in[1];
    const float* sf   = (const float*)d_in[2];
    const float* W    = (const float*)d_in[3];
    const float* A    = (const float*)d_in[4];
    const float* bemb = (const float*)d_in[5];
    const float* px_r = (const float*)d_in[6];
    float* out = (float*)d_out;

    const int N  = in_sizes[1];        // 1024
    const int G  = in_sizes[6];        // 10000
    const int NB = in_sizes[5] / G;    // 64

    dim3 grid(XG, NB + 1);
    fused_decoder_kernel<<<grid, THREADS>>>(z, bc, sf, W, A, bemb, px_r, out, N, G, NB);
}